// round 10
// baseline (speedup 1.0000x reference)
#include <cuda_runtime.h>
#include <cuda_bf16.h>
#include <math.h>
#include <stdint.h>

// ---------------- problem constants ----------------
#define NN 4096
#define DD 4096
#define OO 4096
#define EE 8
#define RR 16
#define ER 128      // E*R
#define GG 9        // E+1

// ---------------- device scratch (small — proven safe footprint) ----------------
__device__ float g_gates[NN * GG];      // softmax gates per row (base + 8 experts)
__device__ float g_t[NN * ER];          // gated LoRA intermediate t'[n, e*16+r]
__device__ float g_At[DD * ER];         // lora_A transposed to [d][e*16+r]

// ---------------- tf32 helpers (sm_80+ baseline ISA) ----------------
__device__ __forceinline__ uint32_t to_tf32(float v) {
    uint32_t r;
    asm("cvt.rna.tf32.f32 %0, %1;" : "=r"(r) : "f"(v));
    return r;
}
__device__ __forceinline__ void mma_tf32(float* c, const uint32_t* a, const uint32_t* b) {
    asm volatile(
        "mma.sync.aligned.m16n8k8.row.col.f32.tf32.tf32.f32 "
        "{%0,%1,%2,%3}, {%4,%5,%6,%7}, {%8,%9}, {%0,%1,%2,%3};"
        : "+f"(c[0]), "+f"(c[1]), "+f"(c[2]), "+f"(c[3])
        : "r"(a[0]), "r"(a[1]), "r"(a[2]), "r"(a[3]), "r"(b[0]), "r"(b[1]));
}

// ---------------- kernel 1: gate logits + top2 + softmax (R1-proven) ----------------
__global__ void gate_kernel(const float* __restrict__ x,
                            const float* __restrict__ gw)
{
    int warp = (blockIdx.x * blockDim.x + threadIdx.x) >> 5;
    int lane = threadIdx.x & 31;
    if (warp >= NN) return;
    const float* xr = x + (size_t)warp * DD;

    float acc[GG];
#pragma unroll
    for (int c = 0; c < GG; c++) acc[c] = 0.f;

    for (int d = lane; d < DD; d += 32) {
        float xv = xr[d];
#pragma unroll
        for (int c = 0; c < GG; c++)
            acc[c] += xv * gw[c * DD + d];
    }
#pragma unroll
    for (int c = 0; c < GG; c++) {
#pragma unroll
        for (int off = 16; off > 0; off >>= 1)
            acc[c] += __shfl_xor_sync(0xFFFFFFFFu, acc[c], off);
    }

    if (lane == 0) {
        float m1 = -INFINITY, m2 = -INFINITY;
        int i1 = -1, i2 = -1;
#pragma unroll
        for (int c = 1; c < GG; c++) {
            float v = acc[c];
            if (v > m1) { m2 = m1; i2 = i1; m1 = v; i1 = c; }
            else if (v > m2) { m2 = v; i2 = c; }
        }
        float vals[GG];
        vals[0] = acc[0];
#pragma unroll
        for (int c = 1; c < GG; c++)
            vals[c] = (c == i1 || c == i2) ? acc[c] : 0.0f;

        float mx = vals[0];
#pragma unroll
        for (int c = 1; c < GG; c++) mx = fmaxf(mx, vals[c]);
        float s = 0.f;
        float e[GG];
#pragma unroll
        for (int c = 0; c < GG; c++) { e[c] = __expf(vals[c] - mx); s += e[c]; }
        float inv = 1.0f / s;
#pragma unroll
        for (int c = 0; c < GG; c++)
            g_gates[warp * GG + c] = e[c] * inv;
    }
}

// ---------------- kernel 2: transpose lora_A -> [d][e*16+r] (R1-proven) ----------------
__global__ void transpose_A_kernel(const float* __restrict__ loraA)
{
    int total = EE * DD * RR;
    for (int i = blockIdx.x * blockDim.x + threadIdx.x; i < total;
         i += gridDim.x * blockDim.x) {
        int e = i / (DD * RR);
        int d = (i / RR) % DD;
        int r = i % RR;
        g_At[d * ER + e * RR + r] = loraA[i];
    }
}

// ---------------- kernel 3: t'[n,c] = gate[n,1+c/16] * (x@At)[n,c] (R1-proven) ----
__global__ void loraA_kernel(const float* __restrict__ x)
{
    __shared__ float xs[16][32];
    __shared__ float as[16][ER];

    int tid  = threadIdx.x;
    int tcol = tid & 31;
    int trow = tid >> 5;
    int rowBase = blockIdx.x * 32;

    float acc[4][4];
#pragma unroll
    for (int i = 0; i < 4; i++)
#pragma unroll
        for (int j = 0; j < 4; j++) acc[i][j] = 0.f;

    for (int k0 = 0; k0 < DD; k0 += 16) {
#pragma unroll
        for (int j = 0; j < 2; j++) {
            int i = tid * 2 + j;
            int row = i >> 4;
            int kk  = i & 15;
            xs[kk][row] = x[(size_t)(rowBase + row) * DD + k0 + kk];
        }
#pragma unroll
        for (int j = 0; j < 2; j++) {
            int i = tid + j * 256;
            int kk = i >> 5;
            int c4 = i & 31;
            *(float4*)&as[kk][c4 * 4] =
                *(const float4*)&g_At[(size_t)(k0 + kk) * ER + c4 * 4];
        }
        __syncthreads();
#pragma unroll
        for (int kk = 0; kk < 16; kk++) {
            float ra[4], rb[4];
            *(float4*)ra = *(const float4*)&xs[kk][trow * 4];
            *(float4*)rb = *(const float4*)&as[kk][tcol * 4];
#pragma unroll
            for (int i = 0; i < 4; i++)
#pragma unroll
                for (int j = 0; j < 4; j++)
                    acc[i][j] += ra[i] * rb[j];
        }
        __syncthreads();
    }
#pragma unroll
    for (int i = 0; i < 4; i++) {
        int row = rowBase + trow * 4 + i;
#pragma unroll
        for (int j = 0; j < 4; j++) {
            int col = tcol * 4 + j;
            float g = g_gates[row * GG + 1 + (col >> 4)];
            g_t[(size_t)row * ER + col] = g * acc[i][j];
        }
    }
}

// ---------------- kernel 4: pipelined tf32 tensor-core GEMM, 128x256 block ----------------
// acc = x@W (512 chunks of K=8), then acc *= g0, then acc += t'@B_flat (16 chunks),
// epilogue: out = acc + g0*bias.  Single-pass tf32 (cvt.rna), fp32 accumulators.
// BM=128, BN=256, BK=8; 8 warps (2x4), warp tile 64x64 (4 mi x 8 ni); 256 threads.
// 2-stage reg-relay pipeline: convst(c+1) -> ldreg(c+2) -> compute(c) -> sync.
#define SA 12    // A smem stride in u32 (8 + pad4): frag banks 12*gid+tig all distinct
#define SB 264   // B smem stride in u32 (256 + pad8): frag banks 8*tig+gid distinct
#define NC0 512  // chunks in base GEMM (4096/8)
#define NC  528  // + 16 lora chunks (128/8)

__global__ void __launch_bounds__(256, 1) mma_fused_kernel(const float* __restrict__ x,
                                                           const float* __restrict__ W,
                                                           const float* __restrict__ bias,
                                                           const float* __restrict__ loraB,
                                                           float* __restrict__ out)
{
    __shared__ __align__(16) uint32_t At[2][128][SA];   // 12288 B
    __shared__ __align__(16) uint32_t Bt[2][8][SB];     // 16896 B

    int tid  = threadIdx.x;
    int wid  = tid >> 5;
    int lane = tid & 31;
    int gid  = lane >> 2;   // 0..7
    int tig  = lane & 3;    // 0..3
    int wm = wid >> 2;      // 0..1 (m offset *64)
    int wn = wid & 3;       // 0..3 (n offset *64)
    int rowBase = blockIdx.y * 128;
    int colBase = blockIdx.x * 256;

    float acc[4][8][4];
#pragma unroll
    for (int mi = 0; mi < 4; mi++)
#pragma unroll
        for (int ni = 0; ni < 8; ni++)
#pragma unroll
            for (int q = 0; q < 4; q++) acc[mi][ni][q] = 0.f;

    // per-thread tile slots:
    // A tile (128x8 fp32 = 256 float4): row = tid>>1, half = tid&1
    // B tile (8x256 fp32 = 512 float4): i = tid + j*256 -> kr = i>>6, q = i&63
    int arow = tid >> 1, ahalf = tid & 1;
    int bq = tid & 63;

    float4 ra, rb[2];

    auto ldreg = [&](int c) {
        const float *Asrc, *Bsrc;
        int Kp, k0;
        if (c < NC0) { Asrc = x;   Bsrc = W;     Kp = DD; k0 = c * 8; }
        else         { Asrc = g_t; Bsrc = loraB; Kp = ER; k0 = (c - NC0) * 8; }
        ra = *(const float4*)&Asrc[(size_t)(rowBase + arow) * Kp + k0 + ahalf * 4];
        int kr0 = tid >> 6;           // 0..3
        rb[0] = *(const float4*)&Bsrc[(size_t)(k0 + kr0) * OO + colBase + bq * 4];
        rb[1] = *(const float4*)&Bsrc[(size_t)(k0 + kr0 + 4) * OO + colBase + bq * 4];
    };

    auto convst = [&](int s) {
        *(uint4*)&At[s][arow][ahalf * 4] =
            make_uint4(to_tf32(ra.x), to_tf32(ra.y), to_tf32(ra.z), to_tf32(ra.w));
        int kr0 = tid >> 6;
        *(uint4*)&Bt[s][kr0][bq * 4] =
            make_uint4(to_tf32(rb[0].x), to_tf32(rb[0].y), to_tf32(rb[0].z), to_tf32(rb[0].w));
        *(uint4*)&Bt[s][kr0 + 4][bq * 4] =
            make_uint4(to_tf32(rb[1].x), to_tf32(rb[1].y), to_tf32(rb[1].z), to_tf32(rb[1].w));
    };

    auto compute = [&](int buf) {
        uint32_t bf[8][2];
#pragma unroll
        for (int ni = 0; ni < 8; ni++) {
            int n = wn * 64 + ni * 8 + gid;
            bf[ni][0] = Bt[buf][tig][n];
            bf[ni][1] = Bt[buf][tig + 4][n];
        }
#pragma unroll
        for (int mi = 0; mi < 4; mi++) {
            int r = wm * 64 + mi * 16 + gid;
            uint32_t af[4];
            af[0] = At[buf][r][tig];
            af[1] = At[buf][r + 8][tig];
            af[2] = At[buf][r][tig + 4];
            af[3] = At[buf][r + 8][tig + 4];
#pragma unroll
            for (int ni = 0; ni < 8; ni++)
                mma_tf32(acc[mi][ni], af, bf[ni]);
        }
    };

    // prologue
    ldreg(0);
    convst(0);
    ldreg(1);
    __syncthreads();

#pragma unroll 1
    for (int c = 0; c < NC; c++) {
        if (c + 1 < NC) convst((c + 1) & 1);   // regs(c+1) -> smem (LDG hidden by prior iter)
        if (c + 2 < NC) ldreg(c + 2);          // issue LDGs two chunks ahead
        if (c == NC0) {
            // base GEMM done: scale accumulators by base gate g0
#pragma unroll
            for (int mi = 0; mi < 4; mi++) {
                int rg = rowBase + wm * 64 + mi * 16 + gid;
                float g0a = g_gates[rg * GG];
                float g0b = g_gates[(rg + 8) * GG];
#pragma unroll
                for (int ni = 0; ni < 8; ni++) {
                    acc[mi][ni][0] *= g0a;
                    acc[mi][ni][1] *= g0a;
                    acc[mi][ni][2] *= g0b;
                    acc[mi][ni][3] *= g0b;
                }
            }
        }
        compute(c & 1);
        __syncthreads();
    }

    // ----- epilogue: out = acc + g0 * bias -----
#pragma unroll
    for (int mi = 0; mi < 4; mi++) {
        int ra2 = rowBase + wm * 64 + mi * 16 + gid;
#pragma unroll
        for (int half = 0; half < 2; half++) {
            int row = ra2 + half * 8;
            float g0 = g_gates[row * GG];
#pragma unroll
            for (int ni = 0; ni < 8; ni++) {
                int col = colBase + wn * 64 + ni * 8 + tig * 2;
                float2 v;
                v.x = acc[mi][ni][half * 2 + 0] + g0 * bias[col];
                v.y = acc[mi][ni][half * 2 + 1] + g0 * bias[col + 1];
                *(float2*)&out[(size_t)row * OO + col] = v;
            }
        }
    }
}

// ---------------- launcher ----------------
extern "C" void kernel_launch(void* const* d_in, const int* in_sizes, int n_in,
                              void* d_out, int out_size)
{
    const float* x      = (const float*)d_in[0];
    const float* W      = (const float*)d_in[1];
    const float* bias   = (const float*)d_in[2];
    const float* loraA  = (const float*)d_in[3];
    const float* loraB  = (const float*)d_in[4];
    const float* gw     = (const float*)d_in[5];
    // d_in[6] = bvv (unused by the reference computation)
    float* out = (float*)d_out;

    gate_kernel<<<NN / 8, 256>>>(x, gw);
    transpose_A_kernel<<<512, 256>>>(loraA);
    loraA_kernel<<<NN / 32, 256>>>(x);
    mma_fused_kernel<<<dim3(OO / 256, NN / 128), 256>>>(x, W, bias, loraB, out);
}

// round 11
// speedup vs baseline: 1.2427x; 1.2427x over previous
#include <cuda_runtime.h>
#include <cuda_bf16.h>
#include <math.h>
#include <stdint.h>

// ---------------- problem constants ----------------
#define NN 4096
#define DD 4096
#define OO 4096
#define EE 8
#define RR 16
#define ER 128      // E*R
#define GG 9        // E+1

// ---------------- device scratch (small — proven safe footprint) ----------------
__device__ float g_gates[NN * GG];      // softmax gates per row (base + 8 experts)
__device__ float g_t[NN * ER];          // gated LoRA intermediate t'[n, e*16+r]
__device__ float g_At[DD * ER];         // lora_A transposed to [d][e*16+r]

// ---------------- tf32 helpers (sm_80+ baseline ISA) ----------------
__device__ __forceinline__ uint32_t to_tf32(float v) {
    uint32_t r;
    asm("cvt.rna.tf32.f32 %0, %1;" : "=r"(r) : "f"(v));
    return r;
}
__device__ __forceinline__ void mma_tf32(float* c, const uint32_t* a, const uint32_t* b) {
    asm volatile(
        "mma.sync.aligned.m16n8k8.row.col.f32.tf32.tf32.f32 "
        "{%0,%1,%2,%3}, {%4,%5,%6,%7}, {%8,%9}, {%0,%1,%2,%3};"
        : "+f"(c[0]), "+f"(c[1]), "+f"(c[2]), "+f"(c[3])
        : "r"(a[0]), "r"(a[1]), "r"(a[2]), "r"(a[3]), "r"(b[0]), "r"(b[1]));
}

// ---------------- kernel 1: gate logits + top2 + softmax (R1-proven) ----------------
__global__ void gate_kernel(const float* __restrict__ x,
                            const float* __restrict__ gw)
{
    int warp = (blockIdx.x * blockDim.x + threadIdx.x) >> 5;
    int lane = threadIdx.x & 31;
    if (warp >= NN) return;
    const float* xr = x + (size_t)warp * DD;

    float acc[GG];
#pragma unroll
    for (int c = 0; c < GG; c++) acc[c] = 0.f;

    for (int d = lane; d < DD; d += 32) {
        float xv = xr[d];
#pragma unroll
        for (int c = 0; c < GG; c++)
            acc[c] += xv * gw[c * DD + d];
    }
#pragma unroll
    for (int c = 0; c < GG; c++) {
#pragma unroll
        for (int off = 16; off > 0; off >>= 1)
            acc[c] += __shfl_xor_sync(0xFFFFFFFFu, acc[c], off);
    }

    if (lane == 0) {
        float m1 = -INFINITY, m2 = -INFINITY;
        int i1 = -1, i2 = -1;
#pragma unroll
        for (int c = 1; c < GG; c++) {
            float v = acc[c];
            if (v > m1) { m2 = m1; i2 = i1; m1 = v; i1 = c; }
            else if (v > m2) { m2 = v; i2 = c; }
        }
        float vals[GG];
        vals[0] = acc[0];
#pragma unroll
        for (int c = 1; c < GG; c++)
            vals[c] = (c == i1 || c == i2) ? acc[c] : 0.0f;

        float mx = vals[0];
#pragma unroll
        for (int c = 1; c < GG; c++) mx = fmaxf(mx, vals[c]);
        float s = 0.f;
        float e[GG];
#pragma unroll
        for (int c = 0; c < GG; c++) { e[c] = __expf(vals[c] - mx); s += e[c]; }
        float inv = 1.0f / s;
#pragma unroll
        for (int c = 0; c < GG; c++)
            g_gates[warp * GG + c] = e[c] * inv;
    }
}

// ---------------- kernel 2: transpose lora_A -> [d][e*16+r] (R1-proven) ----------------
__global__ void transpose_A_kernel(const float* __restrict__ loraA)
{
    int total = EE * DD * RR;
    for (int i = blockIdx.x * blockDim.x + threadIdx.x; i < total;
         i += gridDim.x * blockDim.x) {
        int e = i / (DD * RR);
        int d = (i / RR) % DD;
        int r = i % RR;
        g_At[d * ER + e * RR + r] = loraA[i];
    }
}

// ---------------- kernel 3: t'[n,c] = gate[n,1+c/16] * (x@At)[n,c] (R1-proven) ----
__global__ void loraA_kernel(const float* __restrict__ x)
{
    __shared__ float xs[16][32];
    __shared__ float as[16][ER];

    int tid  = threadIdx.x;
    int tcol = tid & 31;
    int trow = tid >> 5;
    int rowBase = blockIdx.x * 32;

    float acc[4][4];
#pragma unroll
    for (int i = 0; i < 4; i++)
#pragma unroll
        for (int j = 0; j < 4; j++) acc[i][j] = 0.f;

    for (int k0 = 0; k0 < DD; k0 += 16) {
#pragma unroll
        for (int j = 0; j < 2; j++) {
            int i = tid * 2 + j;
            int row = i >> 4;
            int kk  = i & 15;
            xs[kk][row] = x[(size_t)(rowBase + row) * DD + k0 + kk];
        }
#pragma unroll
        for (int j = 0; j < 2; j++) {
            int i = tid + j * 256;
            int kk = i >> 5;
            int c4 = i & 31;
            *(float4*)&as[kk][c4 * 4] =
                *(const float4*)&g_At[(size_t)(k0 + kk) * ER + c4 * 4];
        }
        __syncthreads();
#pragma unroll
        for (int kk = 0; kk < 16; kk++) {
            float ra[4], rb[4];
            *(float4*)ra = *(const float4*)&xs[kk][trow * 4];
            *(float4*)rb = *(const float4*)&as[kk][tcol * 4];
#pragma unroll
            for (int i = 0; i < 4; i++)
#pragma unroll
                for (int j = 0; j < 4; j++)
                    acc[i][j] += ra[i] * rb[j];
        }
        __syncthreads();
    }
#pragma unroll
    for (int i = 0; i < 4; i++) {
        int row = rowBase + trow * 4 + i;
#pragma unroll
        for (int j = 0; j < 4; j++) {
            int col = tcol * 4 + j;
            float g = g_gates[row * GG + 1 + (col >> 4)];
            g_t[(size_t)row * ER + col] = g * acc[i][j];
        }
    }
}

// ---------------- kernel 4: pipelined tf32 tensor-core GEMM ----------------
// acc = x@W (256 chunks of K=16), then acc *= g0, then acc += t'@B_flat (8 chunks),
// epilogue: out = acc + g0*bias.  Single-pass tf32 (cvt.rna), fp32 accumulators.
// BM=BN=128, BK=16; 4 warps (2x2), warp tile 64x64 (4 mi x 8 ni); 128 threads.
// 2 CTAs/SM (reg-capped); 2-stage reg-relay pipeline (R9-proven ordering).
#define SA 20    // A smem stride in u32 (16 + pad4): frag banks 20*gid+tig all distinct
#define SB 136   // B smem stride in u32 (128 + pad8): frag banks 8*tig+gid distinct
#define NC0 256  // chunks in base GEMM (4096/16)
#define NC  264  // + 8 lora chunks (128/16)

__global__ void __launch_bounds__(128, 2) mma_fused_kernel(const float* __restrict__ x,
                                                           const float* __restrict__ W,
                                                           const float* __restrict__ bias,
                                                           const float* __restrict__ loraB,
                                                           float* __restrict__ out)
{
    __shared__ __align__(16) uint32_t At[2][128][SA];   // 20480 B
    __shared__ __align__(16) uint32_t Bt[2][16][SB];    // 17408 B

    int tid  = threadIdx.x;
    int wid  = tid >> 5;
    int lane = tid & 31;
    int gid  = lane >> 2;   // 0..7
    int tig  = lane & 3;    // 0..3
    int wm = wid >> 1;      // 0..1 (m offset *64)
    int wn = wid & 1;       // 0..1 (n offset *64)
    int rowBase = blockIdx.y * 128;
    int colBase = blockIdx.x * 128;

    float acc[4][8][4];
#pragma unroll
    for (int mi = 0; mi < 4; mi++)
#pragma unroll
        for (int ni = 0; ni < 8; ni++)
#pragma unroll
            for (int q = 0; q < 4; q++) acc[mi][ni][q] = 0.f;

    // per-thread tile slots (128 threads):
    // A tile (128x16 fp32 = 512 float4): slot j: row = (tid>>2)+32j, q = tid&3
    // B tile (16x128 fp32 = 512 float4): slot j: kr = (tid>>5)+4j,  q = tid&31
    int arow = tid >> 2, aq = tid & 3;
    int bkr  = tid >> 5, bq = tid & 31;

    float4 ra[4], rb[4];

    auto ldreg = [&](int c) {
        const float *Asrc, *Bsrc;
        int Kp, k0;
        if (c < NC0) { Asrc = x;   Bsrc = W;     Kp = DD; k0 = c * 16; }
        else         { Asrc = g_t; Bsrc = loraB; Kp = ER; k0 = (c - NC0) * 16; }
#pragma unroll
        for (int j = 0; j < 4; j++) {
            ra[j] = *(const float4*)&Asrc[(size_t)(rowBase + arow + 32 * j) * Kp + k0 + aq * 4];
            rb[j] = *(const float4*)&Bsrc[(size_t)(k0 + bkr + 4 * j) * OO + colBase + bq * 4];
        }
    };

    auto convst = [&](int s) {
#pragma unroll
        for (int j = 0; j < 4; j++) {
            *(uint4*)&At[s][arow + 32 * j][aq * 4] =
                make_uint4(to_tf32(ra[j].x), to_tf32(ra[j].y), to_tf32(ra[j].z), to_tf32(ra[j].w));
            *(uint4*)&Bt[s][bkr + 4 * j][bq * 4] =
                make_uint4(to_tf32(rb[j].x), to_tf32(rb[j].y), to_tf32(rb[j].z), to_tf32(rb[j].w));
        }
    };

    auto compute = [&](int buf) {
#pragma unroll
        for (int s = 0; s < 2; s++) {
            int k0 = s * 8 + tig;
            uint32_t bf[8][2];
#pragma unroll
            for (int ni = 0; ni < 8; ni++) {
                int n = wn * 64 + ni * 8 + gid;
                bf[ni][0] = Bt[buf][k0][n];
                bf[ni][1] = Bt[buf][k0 + 4][n];
            }
#pragma unroll
            for (int mi = 0; mi < 4; mi++) {
                int r = wm * 64 + mi * 16 + gid;
                uint32_t af[4];
                af[0] = At[buf][r][k0];
                af[1] = At[buf][r + 8][k0];
                af[2] = At[buf][r][k0 + 4];
                af[3] = At[buf][r + 8][k0 + 4];
#pragma unroll
                for (int ni = 0; ni < 8; ni++)
                    mma_tf32(acc[mi][ni], af, bf[ni]);
            }
        }
    };

    // prologue
    ldreg(0);
    convst(0);
    __syncthreads();

#pragma unroll 1
    for (int c = 0; c < NC; c++) {
        if (c + 1 < NC) ldreg(c + 1);       // LDGs in flight, hidden by compute
        if (c == NC0) {
            // base GEMM done: scale accumulators by base gate g0
#pragma unroll
            for (int mi = 0; mi < 4; mi++) {
                int rg = rowBase + wm * 64 + mi * 16 + gid;
                float g0a = g_gates[rg * GG];
                float g0b = g_gates[(rg + 8) * GG];
#pragma unroll
                for (int ni = 0; ni < 8; ni++) {
                    acc[mi][ni][0] *= g0a;
                    acc[mi][ni][1] *= g0a;
                    acc[mi][ni][2] *= g0b;
                    acc[mi][ni][3] *= g0b;
                }
            }
        }
        compute(c & 1);
        if (c + 1 < NC) convst((c + 1) & 1);
        __syncthreads();
    }

    // ----- epilogue: out = acc + g0 * bias -----
#pragma unroll
    for (int mi = 0; mi < 4; mi++) {
        int ra2 = rowBase + wm * 64 + mi * 16 + gid;
#pragma unroll
        for (int half = 0; half < 2; half++) {
            int row = ra2 + half * 8;
            float g0 = g_gates[row * GG];
#pragma unroll
            for (int ni = 0; ni < 8; ni++) {
                int col = colBase + wn * 64 + ni * 8 + tig * 2;
                float2 v;
                v.x = acc[mi][ni][half * 2 + 0] + g0 * bias[col];
                v.y = acc[mi][ni][half * 2 + 1] + g0 * bias[col + 1];
                *(float2*)&out[(size_t)row * OO + col] = v;
            }
        }
    }
}

// ---------------- launcher ----------------
extern "C" void kernel_launch(void* const* d_in, const int* in_sizes, int n_in,
                              void* d_out, int out_size)
{
    const float* x      = (const float*)d_in[0];
    const float* W      = (const float*)d_in[1];
    const float* bias   = (const float*)d_in[2];
    const float* loraA  = (const float*)d_in[3];
    const float* loraB  = (const float*)d_in[4];
    const float* gw     = (const float*)d_in[5];
    // d_in[6] = bvv (unused by the reference computation)
    float* out = (float*)d_out;

    gate_kernel<<<NN / 8, 256>>>(x, gw);
    transpose_A_kernel<<<512, 256>>>(loraA);
    loraA_kernel<<<NN / 32, 256>>>(x);
    mma_fused_kernel<<<dim3(OO / 128, NN / 128), 128>>>(x, W, bias, loraB, out);
}

// round 12
// speedup vs baseline: 1.2752x; 1.0262x over previous
#include <cuda_runtime.h>
#include <cuda_bf16.h>
#include <math.h>
#include <stdint.h>

// ---------------- problem constants ----------------
#define NN 4096
#define DD 4096
#define OO 4096
#define EE 8
#define RR 16
#define ER 128      // E*R
#define GG 9        // E+1

// ---------------- device scratch (small — proven safe footprint) ----------------
__device__ float g_gates[NN * GG];      // softmax gates per row (base + 8 experts)
__device__ float g_t[NN * ER];          // gated LoRA intermediate t'[n, e*16+r]
__device__ float g_At[DD * ER];         // lora_A transposed to [d][e*16+r]

// ---------------- tf32 helpers (sm_80+ baseline ISA) ----------------
__device__ __forceinline__ uint32_t to_tf32(float v) {
    uint32_t r;
    asm("cvt.rna.tf32.f32 %0, %1;" : "=r"(r) : "f"(v));
    return r;
}
__device__ __forceinline__ void mma_tf32(float* c, const uint32_t* a, const uint32_t* b) {
    asm volatile(
        "mma.sync.aligned.m16n8k8.row.col.f32.tf32.tf32.f32 "
        "{%0,%1,%2,%3}, {%4,%5,%6,%7}, {%8,%9}, {%0,%1,%2,%3};"
        : "+f"(c[0]), "+f"(c[1]), "+f"(c[2]), "+f"(c[3])
        : "r"(a[0]), "r"(a[1]), "r"(a[2]), "r"(a[3]), "r"(b[0]), "r"(b[1]));
}

// ---------------- kernel 1: transpose lora_A -> [d][e*16+r] (R1-proven) ----------------
__global__ void transpose_A_kernel(const float* __restrict__ loraA)
{
    int total = EE * DD * RR;
    for (int i = blockIdx.x * blockDim.x + threadIdx.x; i < total;
         i += gridDim.x * blockDim.x) {
        int e = i / (DD * RR);
        int d = (i / RR) % DD;
        int r = i % RR;
        g_At[d * ER + e * RR + r] = loraA[i];
    }
}

// ---------------- kernel 2: FUSED gate + loraA ----------------
// Per 32-row block: one pass over x computes BOTH the 9 fp32 gate logits
// (exact fp32 — tf32 would risk top-2 flips) and the x@At tile.
// Then in-block: top-2 + softmax -> g_gates, and t' = gate * (x@At) -> g_t.
__global__ void __launch_bounds__(256) fused_gate_loraA_kernel(const float* __restrict__ x,
                                                               const float* __restrict__ gw)
{
    __shared__ float xs[16][32];        // x tile, transposed (k, row)
    __shared__ float as[16][ER];        // At tile
    __shared__ float gs[16][GG];        // gw chunk (k, col)
    __shared__ float gpart[8][32][GG];  // gate partials [warp][row][col]
    __shared__ float grow[32][GG];      // final gates for this block's rows

    int tid  = threadIdx.x;
    int wrp  = tid >> 5;    // 0..7
    int lane = tid & 31;    // 0..31  (= row for gate path)
    int tcol = tid & 31;
    int trow = tid >> 5;
    int rowBase = blockIdx.x * 32;

    float acc[4][4];
#pragma unroll
    for (int i = 0; i < 4; i++)
#pragma unroll
        for (int j = 0; j < 4; j++) acc[i][j] = 0.f;

    float gacc[GG];
#pragma unroll
    for (int c = 0; c < GG; c++) gacc[c] = 0.f;

    for (int k0 = 0; k0 < DD; k0 += 16) {
#pragma unroll
        for (int j = 0; j < 2; j++) {
            int i = tid * 2 + j;
            int row = i >> 4;
            int kk  = i & 15;
            xs[kk][row] = x[(size_t)(rowBase + row) * DD + k0 + kk];
        }
#pragma unroll
        for (int j = 0; j < 2; j++) {
            int i = tid + j * 256;
            int kk = i >> 5;
            int c4 = i & 31;
            *(float4*)&as[kk][c4 * 4] =
                *(const float4*)&g_At[(size_t)(k0 + kk) * ER + c4 * 4];
        }
        if (tid < 16 * GG) {            // 144 threads load the gw chunk
            int kk = tid & 15;
            int c  = tid >> 4;
            gs[kk][c] = gw[c * DD + k0 + kk];
        }
        __syncthreads();

        // ---- loraA 4x4 tile FMAs (R1-proven) ----
#pragma unroll
        for (int kk = 0; kk < 16; kk++) {
            float ra[4], rb[4];
            *(float4*)ra = *(const float4*)&xs[kk][trow * 4];
            *(float4*)rb = *(const float4*)&as[kk][tcol * 4];
#pragma unroll
            for (int i = 0; i < 4; i++)
#pragma unroll
                for (int j = 0; j < 4; j++)
                    acc[i][j] += ra[i] * rb[j];
        }

        // ---- gate partials: warp w covers kk = 2w, 2w+1; lane = row ----
        {
            float xv0 = xs[wrp * 2][lane];       // bank = lane: conflict-free
            float xv1 = xs[wrp * 2 + 1][lane];
#pragma unroll
            for (int c = 0; c < GG; c++)
                gacc[c] += xv0 * gs[wrp * 2][c] + xv1 * gs[wrp * 2 + 1][c];
        }
        __syncthreads();
    }

    // ---- reduce gate partials across the 8 warps ----
#pragma unroll
    for (int c = 0; c < GG; c++) gpart[wrp][lane][c] = gacc[c];
    __syncthreads();

    if (tid < 32) {
        float logit[GG];
#pragma unroll
        for (int c = 0; c < GG; c++) {
            float s = 0.f;
#pragma unroll
            for (int w = 0; w < 8; w++) s += gpart[w][tid][c];
            logit[c] = s;
        }
        // top-2 over experts (cols 1..8)
        float m1 = -INFINITY, m2 = -INFINITY;
        int i1 = -1, i2 = -1;
#pragma unroll
        for (int c = 1; c < GG; c++) {
            float v = logit[c];
            if (v > m1) { m2 = m1; i2 = i1; m1 = v; i1 = c; }
            else if (v > m2) { m2 = v; i2 = c; }
        }
        float vals[GG];
        vals[0] = logit[0];
#pragma unroll
        for (int c = 1; c < GG; c++)
            vals[c] = (c == i1 || c == i2) ? logit[c] : 0.0f;
        float mx = vals[0];
#pragma unroll
        for (int c = 1; c < GG; c++) mx = fmaxf(mx, vals[c]);
        float s = 0.f, e[GG];
#pragma unroll
        for (int c = 0; c < GG; c++) { e[c] = __expf(vals[c] - mx); s += e[c]; }
        float inv = 1.0f / s;
#pragma unroll
        for (int c = 0; c < GG; c++) {
            float g = e[c] * inv;
            grow[tid][c] = g;
            g_gates[(rowBase + tid) * GG + c] = g;
        }
    }
    __syncthreads();

    // ---- write t' = gate * (x@At) ----
#pragma unroll
    for (int i = 0; i < 4; i++) {
        int rloc = trow * 4 + i;
#pragma unroll
        for (int j = 0; j < 4; j++) {
            int col = tcol * 4 + j;
            float g = grow[rloc][1 + (col >> 4)];
            g_t[(size_t)(rowBase + rloc) * ER + col] = g * acc[i][j];
        }
    }
}

// ---------------- kernel 3: pipelined tf32 tensor-core GEMM (R11-proven, verbatim) ----------------
// acc = x@W (256 chunks of K=16), then acc *= g0, then acc += t'@B_flat (8 chunks),
// epilogue: out = acc + g0*bias.  Single-pass tf32 (cvt.rna), fp32 accumulators.
// BM=BN=128, BK=16; 4 warps (2x2), warp tile 64x64 (4 mi x 8 ni); 128 threads.
// 2 CTAs/SM (reg-capped); 2-stage reg-relay pipeline (R9-proven ordering).
#define SA 20    // A smem stride in u32 (16 + pad4): frag banks 20*gid+tig all distinct
#define SB 136   // B smem stride in u32 (128 + pad8): frag banks 8*tig+gid distinct
#define NC0 256  // chunks in base GEMM (4096/16)
#define NC  264  // + 8 lora chunks (128/16)

__global__ void __launch_bounds__(128, 2) mma_fused_kernel(const float* __restrict__ x,
                                                           const float* __restrict__ W,
                                                           const float* __restrict__ bias,
                                                           const float* __restrict__ loraB,
                                                           float* __restrict__ out)
{
    __shared__ __align__(16) uint32_t At[2][128][SA];   // 20480 B
    __shared__ __align__(16) uint32_t Bt[2][16][SB];    // 17408 B

    int tid  = threadIdx.x;
    int wid  = tid >> 5;
    int lane = tid & 31;
    int gid  = lane >> 2;   // 0..7
    int tig  = lane & 3;    // 0..3
    int wm = wid >> 1;      // 0..1 (m offset *64)
    int wn = wid & 1;       // 0..1 (n offset *64)
    int rowBase = blockIdx.y * 128;
    int colBase = blockIdx.x * 128;

    float acc[4][8][4];
#pragma unroll
    for (int mi = 0; mi < 4; mi++)
#pragma unroll
        for (int ni = 0; ni < 8; ni++)
#pragma unroll
            for (int q = 0; q < 4; q++) acc[mi][ni][q] = 0.f;

    int arow = tid >> 2, aq = tid & 3;
    int bkr  = tid >> 5, bq = tid & 31;

    float4 ra[4], rb[4];

    auto ldreg = [&](int c) {
        const float *Asrc, *Bsrc;
        int Kp, k0;
        if (c < NC0) { Asrc = x;   Bsrc = W;     Kp = DD; k0 = c * 16; }
        else         { Asrc = g_t; Bsrc = loraB; Kp = ER; k0 = (c - NC0) * 16; }
#pragma unroll
        for (int j = 0; j < 4; j++) {
            ra[j] = *(const float4*)&Asrc[(size_t)(rowBase + arow + 32 * j) * Kp + k0 + aq * 4];
            rb[j] = *(const float4*)&Bsrc[(size_t)(k0 + bkr + 4 * j) * OO + colBase + bq * 4];
        }
    };

    auto convst = [&](int s) {
#pragma unroll
        for (int j = 0; j < 4; j++) {
            *(uint4*)&At[s][arow + 32 * j][aq * 4] =
                make_uint4(to_tf32(ra[j].x), to_tf32(ra[j].y), to_tf32(ra[j].z), to_tf32(ra[j].w));
            *(uint4*)&Bt[s][bkr + 4 * j][bq * 4] =
                make_uint4(to_tf32(rb[j].x), to_tf32(rb[j].y), to_tf32(rb[j].z), to_tf32(rb[j].w));
        }
    };

    auto compute = [&](int buf) {
#pragma unroll
        for (int s = 0; s < 2; s++) {
            int k0 = s * 8 + tig;
            uint32_t bf[8][2];
#pragma unroll
            for (int ni = 0; ni < 8; ni++) {
                int n = wn * 64 + ni * 8 + gid;
                bf[ni][0] = Bt[buf][k0][n];
                bf[ni][1] = Bt[buf][k0 + 4][n];
            }
#pragma unroll
            for (int mi = 0; mi < 4; mi++) {
                int r = wm * 64 + mi * 16 + gid;
                uint32_t af[4];
                af[0] = At[buf][r][k0];
                af[1] = At[buf][r + 8][k0];
                af[2] = At[buf][r][k0 + 4];
                af[3] = At[buf][r + 8][k0 + 4];
#pragma unroll
                for (int ni = 0; ni < 8; ni++)
                    mma_tf32(acc[mi][ni], af, bf[ni]);
            }
        }
    };

    // prologue
    ldreg(0);
    convst(0);
    __syncthreads();

#pragma unroll 1
    for (int c = 0; c < NC; c++) {
        if (c + 1 < NC) ldreg(c + 1);       // LDGs in flight, hidden by compute
        if (c == NC0) {
            // base GEMM done: scale accumulators by base gate g0
#pragma unroll
            for (int mi = 0; mi < 4; mi++) {
                int rg = rowBase + wm * 64 + mi * 16 + gid;
                float g0a = g_gates[rg * GG];
                float g0b = g_gates[(rg + 8) * GG];
#pragma unroll
                for (int ni = 0; ni < 8; ni++) {
                    acc[mi][ni][0] *= g0a;
                    acc[mi][ni][1] *= g0a;
                    acc[mi][ni][2] *= g0b;
                    acc[mi][ni][3] *= g0b;
                }
            }
        }
        compute(c & 1);
        if (c + 1 < NC) convst((c + 1) & 1);
        __syncthreads();
    }

    // ----- epilogue: out = acc + g0 * bias -----
#pragma unroll
    for (int mi = 0; mi < 4; mi++) {
        int ra2 = rowBase + wm * 64 + mi * 16 + gid;
#pragma unroll
        for (int half = 0; half < 2; half++) {
            int row = ra2 + half * 8;
            float g0 = g_gates[row * GG];
#pragma unroll
            for (int ni = 0; ni < 8; ni++) {
                int col = colBase + wn * 64 + ni * 8 + tig * 2;
                float2 v;
                v.x = acc[mi][ni][half * 2 + 0] + g0 * bias[col];
                v.y = acc[mi][ni][half * 2 + 1] + g0 * bias[col + 1];
                *(float2*)&out[(size_t)row * OO + col] = v;
            }
        }
    }
}

// ---------------- launcher ----------------
extern "C" void kernel_launch(void* const* d_in, const int* in_sizes, int n_in,
                              void* d_out, int out_size)
{
    const float* x      = (const float*)d_in[0];
    const float* W      = (const float*)d_in[1];
    const float* bias   = (const float*)d_in[2];
    const float* loraA  = (const float*)d_in[3];
    const float* loraB  = (const float*)d_in[4];
    const float* gw     = (const float*)d_in[5];
    // d_in[6] = bvv (unused by the reference computation)
    float* out = (float*)d_out;

    transpose_A_kernel<<<512, 256>>>(loraA);
    fused_gate_loraA_kernel<<<NN / 32, 256>>>(x, gw);
    mma_fused_kernel<<<dim3(OO / 128, NN / 128), 128>>>(x, W, bias, loraB, out);
}

// round 13
// speedup vs baseline: 1.4728x; 1.1550x over previous
#include <cuda_runtime.h>
#include <cuda_bf16.h>
#include <math.h>
#include <stdint.h>

// ---------------- problem constants ----------------
#define NN 4096
#define DD 4096
#define OO 4096
#define EE 8
#define RR 16
#define ER 128      // E*R
#define GG 9        // E+1
#define NSPLIT 8    // K-splits for the loraA tensor-core GEMM

// ---------------- device scratch ----------------
__device__ float g_gates[NN * GG];              // softmax gates per row
__device__ float g_t[NN * ER];                  // gated LoRA intermediate t'
__device__ float g_At[DD * ER];                 // lora_A transposed to [d][e*16+r]
__device__ float g_tp[NSPLIT * NN * ER];        // K-split partials of x@At (16 MB)

// ---------------- tf32 helpers (sm_80+ baseline ISA) ----------------
__device__ __forceinline__ uint32_t to_tf32(float v) {
    uint32_t r;
    asm("cvt.rna.tf32.f32 %0, %1;" : "=r"(r) : "f"(v));
    return r;
}
__device__ __forceinline__ void mma_tf32(float* c, const uint32_t* a, const uint32_t* b) {
    asm volatile(
        "mma.sync.aligned.m16n8k8.row.col.f32.tf32.tf32.f32 "
        "{%0,%1,%2,%3}, {%4,%5,%6,%7}, {%8,%9}, {%0,%1,%2,%3};"
        : "+f"(c[0]), "+f"(c[1]), "+f"(c[2]), "+f"(c[3])
        : "r"(a[0]), "r"(a[1]), "r"(a[2]), "r"(a[3]), "r"(b[0]), "r"(b[1]));
}

// ---------------- kernel 1: gate logits + top2 + softmax (R1-proven) ----------------
__global__ void gate_kernel(const float* __restrict__ x,
                            const float* __restrict__ gw)
{
    int warp = (blockIdx.x * blockDim.x + threadIdx.x) >> 5;
    int lane = threadIdx.x & 31;
    if (warp >= NN) return;
    const float* xr = x + (size_t)warp * DD;

    float acc[GG];
#pragma unroll
    for (int c = 0; c < GG; c++) acc[c] = 0.f;

    for (int d = lane; d < DD; d += 32) {
        float xv = xr[d];
#pragma unroll
        for (int c = 0; c < GG; c++)
            acc[c] += xv * gw[c * DD + d];
    }
#pragma unroll
    for (int c = 0; c < GG; c++) {
#pragma unroll
        for (int off = 16; off > 0; off >>= 1)
            acc[c] += __shfl_xor_sync(0xFFFFFFFFu, acc[c], off);
    }

    if (lane == 0) {
        float m1 = -INFINITY, m2 = -INFINITY;
        int i1 = -1, i2 = -1;
#pragma unroll
        for (int c = 1; c < GG; c++) {
            float v = acc[c];
            if (v > m1) { m2 = m1; i2 = i1; m1 = v; i1 = c; }
            else if (v > m2) { m2 = v; i2 = c; }
        }
        float vals[GG];
        vals[0] = acc[0];
#pragma unroll
        for (int c = 1; c < GG; c++)
            vals[c] = (c == i1 || c == i2) ? acc[c] : 0.0f;

        float mx = vals[0];
#pragma unroll
        for (int c = 1; c < GG; c++) mx = fmaxf(mx, vals[c]);
        float s = 0.f;
        float e[GG];
#pragma unroll
        for (int c = 0; c < GG; c++) { e[c] = __expf(vals[c] - mx); s += e[c]; }
        float inv = 1.0f / s;
#pragma unroll
        for (int c = 0; c < GG; c++)
            g_gates[warp * GG + c] = e[c] * inv;
    }
}

// ---------------- kernel 2: transpose lora_A -> [d][e*16+r] (R1-proven) ----------------
__global__ void transpose_A_kernel(const float* __restrict__ loraA)
{
    int total = EE * DD * RR;
    for (int i = blockIdx.x * blockDim.x + threadIdx.x; i < total;
         i += gridDim.x * blockDim.x) {
        int e = i / (DD * RR);
        int d = (i / RR) % DD;
        int r = i % RR;
        g_At[d * ER + e * RR + r] = loraA[i];
    }
}

// ---------------- shared geometry for the tf32 MMA kernels (R11-proven) ----------------
#define SA 20    // A smem stride in u32 (16 + pad4): frag banks 20*gid+tig all distinct
#define SB 136   // B smem stride in u32 (128 + pad8): frag banks 8*tig+gid distinct

// ---------------- kernel 3: loraA tensor-core GEMM, K-split ----------------
// g_tp[split][128-row tile] += x[:, split*512 : (split+1)*512] @ At[same k range]
// BM=128, BN=128(=ER), BK=16, 32 chunks per CTA; 4 warps (2x2) of 64x64; 128 thr.
__global__ void __launch_bounds__(128, 2) loraA_tc_kernel(const float* __restrict__ x)
{
    __shared__ __align__(16) uint32_t At2[2][128][SA];
    __shared__ __align__(16) uint32_t Bt2[2][16][SB];

    int tid  = threadIdx.x;
    int wid  = tid >> 5;
    int lane = tid & 31;
    int gid  = lane >> 2;
    int tig  = lane & 3;
    int wm = wid >> 1;
    int wn = wid & 1;
    int split   = blockIdx.x;               // 0..7
    int rowBase = blockIdx.y * 128;
    int kBase   = split * (DD / NSPLIT);    // 512 per split

    float acc[4][8][4];
#pragma unroll
    for (int mi = 0; mi < 4; mi++)
#pragma unroll
        for (int ni = 0; ni < 8; ni++)
#pragma unroll
            for (int q = 0; q < 4; q++) acc[mi][ni][q] = 0.f;

    int arow = tid >> 2, aq = tid & 3;
    int bkr  = tid >> 5, bq = tid & 31;

    float4 ra[4], rb[4];

    auto ldreg = [&](int c) {
        int k0 = kBase + c * 16;
#pragma unroll
        for (int j = 0; j < 4; j++) {
            ra[j] = *(const float4*)&x[(size_t)(rowBase + arow + 32 * j) * DD + k0 + aq * 4];
            rb[j] = *(const float4*)&g_At[(size_t)(k0 + bkr + 4 * j) * ER + bq * 4];
        }
    };
    auto convst = [&](int s) {
#pragma unroll
        for (int j = 0; j < 4; j++) {
            *(uint4*)&At2[s][arow + 32 * j][aq * 4] =
                make_uint4(to_tf32(ra[j].x), to_tf32(ra[j].y), to_tf32(ra[j].z), to_tf32(ra[j].w));
            *(uint4*)&Bt2[s][bkr + 4 * j][bq * 4] =
                make_uint4(to_tf32(rb[j].x), to_tf32(rb[j].y), to_tf32(rb[j].z), to_tf32(rb[j].w));
        }
    };
    auto compute = [&](int buf) {
#pragma unroll
        for (int s = 0; s < 2; s++) {
            int k0 = s * 8 + tig;
            uint32_t bf[8][2];
#pragma unroll
            for (int ni = 0; ni < 8; ni++) {
                int n = wn * 64 + ni * 8 + gid;
                bf[ni][0] = Bt2[buf][k0][n];
                bf[ni][1] = Bt2[buf][k0 + 4][n];
            }
#pragma unroll
            for (int mi = 0; mi < 4; mi++) {
                int r = wm * 64 + mi * 16 + gid;
                uint32_t af[4];
                af[0] = At2[buf][r][k0];
                af[1] = At2[buf][r + 8][k0];
                af[2] = At2[buf][r][k0 + 4];
                af[3] = At2[buf][r + 8][k0 + 4];
#pragma unroll
                for (int ni = 0; ni < 8; ni++)
                    mma_tf32(acc[mi][ni], af, bf[ni]);
            }
        }
    };

    ldreg(0);
    convst(0);
    __syncthreads();

    const int NCH = (DD / NSPLIT) / 16;   // 32
#pragma unroll 1
    for (int c = 0; c < NCH; c++) {
        if (c + 1 < NCH) ldreg(c + 1);
        compute(c & 1);
        if (c + 1 < NCH) convst((c + 1) & 1);
        __syncthreads();
    }

    // write fp32 partials (ungated) to g_tp[split]
    float* tp = g_tp + (size_t)split * NN * ER;
#pragma unroll
    for (int mi = 0; mi < 4; mi++) {
        int ra2 = rowBase + wm * 64 + mi * 16 + gid;
#pragma unroll
        for (int half = 0; half < 2; half++) {
            int row = ra2 + half * 8;
#pragma unroll
            for (int ni = 0; ni < 8; ni++) {
                int col = wn * 64 + ni * 8 + tig * 2;
                float2 v;
                v.x = acc[mi][ni][half * 2 + 0];
                v.y = acc[mi][ni][half * 2 + 1];
                *(float2*)&tp[(size_t)row * ER + col] = v;
            }
        }
    }
}

// ---------------- kernel 4: reduce partials + apply expert gates ----------------
__global__ void reduce_t_kernel()
{
    int i = blockIdx.x * blockDim.x + threadIdx.x;   // float4 index
    const int total = NN * ER / 4;
    if (i >= total) return;
    int row = (i * 4) / ER;
    int col = (i * 4) % ER;                          // 4-col group within one expert
    float4 s = make_float4(0.f, 0.f, 0.f, 0.f);
#pragma unroll
    for (int p = 0; p < NSPLIT; p++) {
        float4 v = ((const float4*)g_tp)[(size_t)p * total + i];
        s.x += v.x; s.y += v.y; s.z += v.z; s.w += v.w;
    }
    float g = g_gates[row * GG + 1 + (col >> 4)];
    s.x *= g; s.y *= g; s.z *= g; s.w *= g;
    ((float4*)g_t)[i] = s;
}

// ---------------- kernel 5: pipelined tf32 tensor-core GEMM (R11-proven, verbatim) ----------------
#define NC0 256  // chunks in base GEMM (4096/16)
#define NC  264  // + 8 lora chunks (128/16)

__global__ void __launch_bounds__(128, 2) mma_fused_kernel(const float* __restrict__ x,
                                                           const float* __restrict__ W,
                                                           const float* __restrict__ bias,
                                                           const float* __restrict__ loraB,
                                                           float* __restrict__ out)
{
    __shared__ __align__(16) uint32_t At[2][128][SA];   // 20480 B
    __shared__ __align__(16) uint32_t Bt[2][16][SB];    // 17408 B

    int tid  = threadIdx.x;
    int wid  = tid >> 5;
    int lane = tid & 31;
    int gid  = lane >> 2;   // 0..7
    int tig  = lane & 3;    // 0..3
    int wm = wid >> 1;      // 0..1 (m offset *64)
    int wn = wid & 1;       // 0..1 (n offset *64)
    int rowBase = blockIdx.y * 128;
    int colBase = blockIdx.x * 128;

    float acc[4][8][4];
#pragma unroll
    for (int mi = 0; mi < 4; mi++)
#pragma unroll
        for (int ni = 0; ni < 8; ni++)
#pragma unroll
            for (int q = 0; q < 4; q++) acc[mi][ni][q] = 0.f;

    int arow = tid >> 2, aq = tid & 3;
    int bkr  = tid >> 5, bq = tid & 31;

    float4 ra[4], rb[4];

    auto ldreg = [&](int c) {
        const float *Asrc, *Bsrc;
        int Kp, k0;
        if (c < NC0) { Asrc = x;   Bsrc = W;     Kp = DD; k0 = c * 16; }
        else         { Asrc = g_t; Bsrc = loraB; Kp = ER; k0 = (c - NC0) * 16; }
#pragma unroll
        for (int j = 0; j < 4; j++) {
            ra[j] = *(const float4*)&Asrc[(size_t)(rowBase + arow + 32 * j) * Kp + k0 + aq * 4];
            rb[j] = *(const float4*)&Bsrc[(size_t)(k0 + bkr + 4 * j) * OO + colBase + bq * 4];
        }
    };

    auto convst = [&](int s) {
#pragma unroll
        for (int j = 0; j < 4; j++) {
            *(uint4*)&At[s][arow + 32 * j][aq * 4] =
                make_uint4(to_tf32(ra[j].x), to_tf32(ra[j].y), to_tf32(ra[j].z), to_tf32(ra[j].w));
            *(uint4*)&Bt[s][bkr + 4 * j][bq * 4] =
                make_uint4(to_tf32(rb[j].x), to_tf32(rb[j].y), to_tf32(rb[j].z), to_tf32(rb[j].w));
        }
    };

    auto compute = [&](int buf) {
#pragma unroll
        for (int s = 0; s < 2; s++) {
            int k0 = s * 8 + tig;
            uint32_t bf[8][2];
#pragma unroll
            for (int ni = 0; ni < 8; ni++) {
                int n = wn * 64 + ni * 8 + gid;
                bf[ni][0] = Bt[buf][k0][n];
                bf[ni][1] = Bt[buf][k0 + 4][n];
            }
#pragma unroll
            for (int mi = 0; mi < 4; mi++) {
                int r = wm * 64 + mi * 16 + gid;
                uint32_t af[4];
                af[0] = At[buf][r][k0];
                af[1] = At[buf][r + 8][k0];
                af[2] = At[buf][r][k0 + 4];
                af[3] = At[buf][r + 8][k0 + 4];
#pragma unroll
                for (int ni = 0; ni < 8; ni++)
                    mma_tf32(acc[mi][ni], af, bf[ni]);
            }
        }
    };

    // prologue
    ldreg(0);
    convst(0);
    __syncthreads();

#pragma unroll 1
    for (int c = 0; c < NC; c++) {
        if (c + 1 < NC) ldreg(c + 1);
        if (c == NC0) {
            // base GEMM done: scale accumulators by base gate g0
#pragma unroll
            for (int mi = 0; mi < 4; mi++) {
                int rg = rowBase + wm * 64 + mi * 16 + gid;
                float g0a = g_gates[rg * GG];
                float g0b = g_gates[(rg + 8) * GG];
#pragma unroll
                for (int ni = 0; ni < 8; ni++) {
                    acc[mi][ni][0] *= g0a;
                    acc[mi][ni][1] *= g0a;
                    acc[mi][ni][2] *= g0b;
                    acc[mi][ni][3] *= g0b;
                }
            }
        }
        compute(c & 1);
        if (c + 1 < NC) convst((c + 1) & 1);
        __syncthreads();
    }

    // ----- epilogue: out = acc + g0 * bias -----
#pragma unroll
    for (int mi = 0; mi < 4; mi++) {
        int ra2 = rowBase + wm * 64 + mi * 16 + gid;
#pragma unroll
        for (int half = 0; half < 2; half++) {
            int row = ra2 + half * 8;
            float g0 = g_gates[row * GG];
#pragma unroll
            for (int ni = 0; ni < 8; ni++) {
                int col = colBase + wn * 64 + ni * 8 + tig * 2;
                float2 v;
                v.x = acc[mi][ni][half * 2 + 0] + g0 * bias[col];
                v.y = acc[mi][ni][half * 2 + 1] + g0 * bias[col + 1];
                *(float2*)&out[(size_t)row * OO + col] = v;
            }
        }
    }
}

// ---------------- launcher ----------------
extern "C" void kernel_launch(void* const* d_in, const int* in_sizes, int n_in,
                              void* d_out, int out_size)
{
    const float* x      = (const float*)d_in[0];
    const float* W      = (const float*)d_in[1];
    const float* bias   = (const float*)d_in[2];
    const float* loraA  = (const float*)d_in[3];
    const float* loraB  = (const float*)d_in[4];
    const float* gw     = (const float*)d_in[5];
    // d_in[6] = bvv (unused by the reference computation)
    float* out = (float*)d_out;

    transpose_A_kernel<<<512, 256>>>(loraA);
    gate_kernel<<<NN / 8, 256>>>(x, gw);
    loraA_tc_kernel<<<dim3(NSPLIT, NN / 128), 128>>>(x);
    reduce_t_kernel<<<NN * ER / 4 / 256, 256>>>();
    mma_fused_kernel<<<dim3(OO / 128, NN / 128), 128>>>(x, W, bias, loraB, out);
}

// round 14
// speedup vs baseline: 1.6178x; 1.0985x over previous
#include <cuda_runtime.h>
#include <cuda_bf16.h>
#include <math.h>
#include <stdint.h>

// ---------------- problem constants ----------------
#define NN 4096
#define DD 4096
#define OO 4096
#define EE 8
#define RR 16
#define ER 128      // E*R
#define GG 9        // E+1
#define NSPLIT 8    // K-splits for the loraA tensor-core GEMM

// ---------------- device scratch ----------------
__device__ float g_gates[NN * GG];              // softmax gates per row
__device__ float g_t[NN * ER];                  // gated LoRA intermediate t'
__device__ float g_At[DD * ER];                 // lora_A transposed to [d][e*16+r]
__device__ float g_tp[NSPLIT * NN * ER];        // K-split partials of x@At (16 MB)

// ---------------- tf32 / async helpers (sm_80+ baseline ISA) ----------------
__device__ __forceinline__ uint32_t to_tf32(float v) {
    uint32_t r;
    asm("cvt.rna.tf32.f32 %0, %1;" : "=r"(r) : "f"(v));
    return r;
}
__device__ __forceinline__ void mma_tf32(float* c, const uint32_t* a, const uint32_t* b) {
    asm volatile(
        "mma.sync.aligned.m16n8k8.row.col.f32.tf32.tf32.f32 "
        "{%0,%1,%2,%3}, {%4,%5,%6,%7}, {%8,%9}, {%0,%1,%2,%3};"
        : "+f"(c[0]), "+f"(c[1]), "+f"(c[2]), "+f"(c[3])
        : "r"(a[0]), "r"(a[1]), "r"(a[2]), "r"(a[3]), "r"(b[0]), "r"(b[1]));
}
__device__ __forceinline__ uint32_t smem_u32(const void* p) {
    uint32_t a;
    asm("{ .reg .u64 t; cvta.to.shared.u64 t, %1; cvt.u32.u64 %0, t; }" : "=r"(a) : "l"(p));
    return a;
}
__device__ __forceinline__ void cp16(uint32_t smem, const void* gmem) {
    asm volatile("cp.async.cg.shared.global [%0], [%1], 16;" :: "r"(smem), "l"(gmem) : "memory");
}
__device__ __forceinline__ void cp_commit() {
    asm volatile("cp.async.commit_group;" ::: "memory");
}
__device__ __forceinline__ void cp_wait2() {
    asm volatile("cp.async.wait_group 2;" ::: "memory");
}

// ---------------- kernel 1: gate logits + top2 + softmax (R1-proven) ----------------
__global__ void gate_kernel(const float* __restrict__ x,
                            const float* __restrict__ gw)
{
    int warp = (blockIdx.x * blockDim.x + threadIdx.x) >> 5;
    int lane = threadIdx.x & 31;
    if (warp >= NN) return;
    const float* xr = x + (size_t)warp * DD;

    float acc[GG];
#pragma unroll
    for (int c = 0; c < GG; c++) acc[c] = 0.f;

    for (int d = lane; d < DD; d += 32) {
        float xv = xr[d];
#pragma unroll
        for (int c = 0; c < GG; c++)
            acc[c] += xv * gw[c * DD + d];
    }
#pragma unroll
    for (int c = 0; c < GG; c++) {
#pragma unroll
        for (int off = 16; off > 0; off >>= 1)
            acc[c] += __shfl_xor_sync(0xFFFFFFFFu, acc[c], off);
    }

    if (lane == 0) {
        float m1 = -INFINITY, m2 = -INFINITY;
        int i1 = -1, i2 = -1;
#pragma unroll
        for (int c = 1; c < GG; c++) {
            float v = acc[c];
            if (v > m1) { m2 = m1; i2 = i1; m1 = v; i1 = c; }
            else if (v > m2) { m2 = v; i2 = c; }
        }
        float vals[GG];
        vals[0] = acc[0];
#pragma unroll
        for (int c = 1; c < GG; c++)
            vals[c] = (c == i1 || c == i2) ? acc[c] : 0.0f;

        float mx = vals[0];
#pragma unroll
        for (int c = 1; c < GG; c++) mx = fmaxf(mx, vals[c]);
        float s = 0.f;
        float e[GG];
#pragma unroll
        for (int c = 0; c < GG; c++) { e[c] = __expf(vals[c] - mx); s += e[c]; }
        float inv = 1.0f / s;
#pragma unroll
        for (int c = 0; c < GG; c++)
            g_gates[warp * GG + c] = e[c] * inv;
    }
}

// ---------------- kernel 2: transpose lora_A -> [d][e*16+r] (R1-proven) ----------------
__global__ void transpose_A_kernel(const float* __restrict__ loraA)
{
    int total = EE * DD * RR;
    for (int i = blockIdx.x * blockDim.x + threadIdx.x; i < total;
         i += gridDim.x * blockDim.x) {
        int e = i / (DD * RR);
        int d = (i / RR) % DD;
        int r = i % RR;
        g_At[d * ER + e * RR + r] = loraA[i];
    }
}

// ---------------- shared geometry for the tf32 MMA kernels (R11-proven) ----------------
#define SA 20    // A smem stride in u32 (16 + pad4): frag banks 20*gid+tig all distinct
#define SB 136   // B smem stride in u32 (128 + pad8): frag banks 8*tig+gid distinct

// ---------------- kernel 3: loraA tensor-core GEMM, K-split (R13-proven, verbatim) ----------------
__global__ void __launch_bounds__(128, 2) loraA_tc_kernel(const float* __restrict__ x)
{
    __shared__ __align__(16) uint32_t At2[2][128][SA];
    __shared__ __align__(16) uint32_t Bt2[2][16][SB];

    int tid  = threadIdx.x;
    int wid  = tid >> 5;
    int lane = tid & 31;
    int gid  = lane >> 2;
    int tig  = lane & 3;
    int wm = wid >> 1;
    int wn = wid & 1;
    int split   = blockIdx.x;               // 0..7
    int rowBase = blockIdx.y * 128;
    int kBase   = split * (DD / NSPLIT);    // 512 per split

    float acc[4][8][4];
#pragma unroll
    for (int mi = 0; mi < 4; mi++)
#pragma unroll
        for (int ni = 0; ni < 8; ni++)
#pragma unroll
            for (int q = 0; q < 4; q++) acc[mi][ni][q] = 0.f;

    int arow = tid >> 2, aq = tid & 3;
    int bkr  = tid >> 5, bq = tid & 31;

    float4 ra[4], rb[4];

    auto ldreg = [&](int c) {
        int k0 = kBase + c * 16;
#pragma unroll
        for (int j = 0; j < 4; j++) {
            ra[j] = *(const float4*)&x[(size_t)(rowBase + arow + 32 * j) * DD + k0 + aq * 4];
            rb[j] = *(const float4*)&g_At[(size_t)(k0 + bkr + 4 * j) * ER + bq * 4];
        }
    };
    auto convst = [&](int s) {
#pragma unroll
        for (int j = 0; j < 4; j++) {
            *(uint4*)&At2[s][arow + 32 * j][aq * 4] =
                make_uint4(to_tf32(ra[j].x), to_tf32(ra[j].y), to_tf32(ra[j].z), to_tf32(ra[j].w));
            *(uint4*)&Bt2[s][bkr + 4 * j][bq * 4] =
                make_uint4(to_tf32(rb[j].x), to_tf32(rb[j].y), to_tf32(rb[j].z), to_tf32(rb[j].w));
        }
    };
    auto compute = [&](int buf) {
#pragma unroll
        for (int s = 0; s < 2; s++) {
            int k0 = s * 8 + tig;
            uint32_t bf[8][2];
#pragma unroll
            for (int ni = 0; ni < 8; ni++) {
                int n = wn * 64 + ni * 8 + gid;
                bf[ni][0] = Bt2[buf][k0][n];
                bf[ni][1] = Bt2[buf][k0 + 4][n];
            }
#pragma unroll
            for (int mi = 0; mi < 4; mi++) {
                int r = wm * 64 + mi * 16 + gid;
                uint32_t af[4];
                af[0] = At2[buf][r][k0];
                af[1] = At2[buf][r + 8][k0];
                af[2] = At2[buf][r][k0 + 4];
                af[3] = At2[buf][r + 8][k0 + 4];
#pragma unroll
                for (int ni = 0; ni < 8; ni++)
                    mma_tf32(acc[mi][ni], af, bf[ni]);
            }
        }
    };

    ldreg(0);
    convst(0);
    __syncthreads();

    const int NCH = (DD / NSPLIT) / 16;   // 32
#pragma unroll 1
    for (int c = 0; c < NCH; c++) {
        if (c + 1 < NCH) ldreg(c + 1);
        compute(c & 1);
        if (c + 1 < NCH) convst((c + 1) & 1);
        __syncthreads();
    }

    float* tp = g_tp + (size_t)split * NN * ER;
#pragma unroll
    for (int mi = 0; mi < 4; mi++) {
        int ra2 = rowBase + wm * 64 + mi * 16 + gid;
#pragma unroll
        for (int half = 0; half < 2; half++) {
            int row = ra2 + half * 8;
#pragma unroll
            for (int ni = 0; ni < 8; ni++) {
                int col = wn * 64 + ni * 8 + tig * 2;
                float2 v;
                v.x = acc[mi][ni][half * 2 + 0];
                v.y = acc[mi][ni][half * 2 + 1];
                *(float2*)&tp[(size_t)row * ER + col] = v;
            }
        }
    }
}

// ---------------- kernel 4: reduce partials + apply expert gates (R13-proven) ----------------
__global__ void reduce_t_kernel()
{
    int i = blockIdx.x * blockDim.x + threadIdx.x;   // float4 index
    const int total = NN * ER / 4;
    if (i >= total) return;
    int row = (i * 4) / ER;
    int col = (i * 4) % ER;
    float4 s = make_float4(0.f, 0.f, 0.f, 0.f);
#pragma unroll
    for (int p = 0; p < NSPLIT; p++) {
        float4 v = ((const float4*)g_tp)[(size_t)p * total + i];
        s.x += v.x; s.y += v.y; s.z += v.z; s.w += v.w;
    }
    float g = g_gates[row * GG + 1 + (col >> 4)];
    s.x *= g; s.y *= g; s.z *= g; s.w *= g;
    ((float4*)g_t)[i] = s;
}

// ---------------- kernel 5: main tf32 GEMM — cp.async 4-stage, inline tf32 cvt ----------------
// acc = x@W (256 chunks of K=16), then acc *= g0, then acc += t'@B_flat (8 chunks),
// epilogue: out = acc + g0*bias.
// BM=BN=128, BK=16; 4 warps (2x2), warp tile 64x64; 128 threads; 2 CTAs/SM.
// Raw fp32 tiles land in 4-stage dynamic smem via cp.async; fragments convert
// to tf32 at load time (cvt.rna), removing reg staging + convert stage.
#define NC0 256  // chunks in base GEMM (4096/16)
#define NC  264  // + 8 lora chunks (128/16)
#define NSTG 4
#define A_U32 (128 * SA)                   // 2560 u32 per A stage
#define B_U32 (16 * SB)                    // 2176 u32 per B stage
#define SMEM_U32 (NSTG * (A_U32 + B_U32))  // 18944 u32 = 75776 B

__global__ void __launch_bounds__(128, 2) mma_fused_kernel(const float* __restrict__ x,
                                                           const float* __restrict__ W,
                                                           const float* __restrict__ bias,
                                                           const float* __restrict__ loraB,
                                                           float* __restrict__ out)
{
    extern __shared__ __align__(16) uint32_t dsm[];
    // A stage s: dsm[s*A_U32 .. ], row r at +r*SA
    // B stage s: dsm[NSTG*A_U32 + s*B_U32 .. ], k-row kr at +kr*SB
    uint32_t* Abase = dsm;
    uint32_t* Bbase = dsm + NSTG * A_U32;

    int tid  = threadIdx.x;
    int wid  = tid >> 5;
    int lane = tid & 31;
    int gid  = lane >> 2;   // 0..7
    int tig  = lane & 3;    // 0..3
    int wm = wid >> 1;      // 0..1 (m offset *64)
    int wn = wid & 1;       // 0..1 (n offset *64)
    int rowBase = blockIdx.y * 128;
    int colBase = blockIdx.x * 128;

    float acc[4][8][4];
#pragma unroll
    for (int mi = 0; mi < 4; mi++)
#pragma unroll
        for (int ni = 0; ni < 8; ni++)
#pragma unroll
            for (int q = 0; q < 4; q++) acc[mi][ni][q] = 0.f;

    // per-thread copy slots (128 threads):
    // A tile (128x16 fp32 = 512 float4): slot j: row = (tid>>2)+32j, q = tid&3
    // B tile (16x128 fp32 = 512 float4): slot j: kr = (tid>>5)+4j,  q = tid&31
    int arow = tid >> 2, aq = tid & 3;
    int bkr  = tid >> 5, bq = tid & 31;

    // precompute smem byte addresses for this thread's copy slots (stage 0)
    uint32_t a_dst0 = smem_u32(&Abase[(size_t)arow * SA + aq * 4]);
    uint32_t b_dst0 = smem_u32(&Bbase[(size_t)bkr * SB + bq * 4]);

    auto issue = [&](int c) {
        const float *Asrc, *Bsrc;
        int Kp, k0;
        if (c < NC0) { Asrc = x;   Bsrc = W;     Kp = DD; k0 = c * 16; }
        else         { Asrc = g_t; Bsrc = loraB; Kp = ER; k0 = (c - NC0) * 16; }
        int s = c & (NSTG - 1);
        uint32_t ad = a_dst0 + (uint32_t)s * (A_U32 * 4);
        uint32_t bd = b_dst0 + (uint32_t)s * (B_U32 * 4);
#pragma unroll
        for (int j = 0; j < 4; j++) {
            cp16(ad + (uint32_t)(32 * j) * (SA * 4),
                 &Asrc[(size_t)(rowBase + arow + 32 * j) * Kp + k0 + aq * 4]);
            cp16(bd + (uint32_t)(4 * j) * (SB * 4),
                 &Bsrc[(size_t)(k0 + bkr + 4 * j) * OO + colBase + bq * 4]);
        }
        cp_commit();
    };

    auto compute = [&](int buf) {
        const uint32_t* Ab = Abase + (size_t)buf * A_U32;
        const uint32_t* Bb = Bbase + (size_t)buf * B_U32;
#pragma unroll
        for (int s = 0; s < 2; s++) {
            int k0 = s * 8 + tig;
            uint32_t bf[8][2];
#pragma unroll
            for (int ni = 0; ni < 8; ni++) {
                int n = wn * 64 + ni * 8 + gid;
                bf[ni][0] = to_tf32(__uint_as_float(Bb[(size_t)k0 * SB + n]));
                bf[ni][1] = to_tf32(__uint_as_float(Bb[(size_t)(k0 + 4) * SB + n]));
            }
#pragma unroll
            for (int mi = 0; mi < 4; mi++) {
                int r = wm * 64 + mi * 16 + gid;
                uint32_t af[4];
                af[0] = to_tf32(__uint_as_float(Ab[(size_t)r * SA + k0]));
                af[1] = to_tf32(__uint_as_float(Ab[(size_t)(r + 8) * SA + k0]));
                af[2] = to_tf32(__uint_as_float(Ab[(size_t)r * SA + k0 + 4]));
                af[3] = to_tf32(__uint_as_float(Ab[(size_t)(r + 8) * SA + k0 + 4]));
#pragma unroll
                for (int ni = 0; ni < 8; ni++)
                    mma_tf32(acc[mi][ni], af, bf[ni]);
            }
        }
    };

    // prologue: fill 3 stages
    issue(0);
    issue(1);
    issue(2);

#pragma unroll 1
    for (int c = 0; c < NC; c++) {
        cp_wait2();            // <=2 groups outstanding -> group c complete
        __syncthreads();       // stage c visible to all; compute(c-1) fully done
        if (c == NC0) {
            // base GEMM done: scale accumulators by base gate g0
#pragma unroll
            for (int mi = 0; mi < 4; mi++) {
                int rg = rowBase + wm * 64 + mi * 16 + gid;
                float g0a = g_gates[rg * GG];
                float g0b = g_gates[(rg + 8) * GG];
#pragma unroll
                for (int ni = 0; ni < 8; ni++) {
                    acc[mi][ni][0] *= g0a;
                    acc[mi][ni][1] *= g0a;
                    acc[mi][ni][2] *= g0b;
                    acc[mi][ni][3] *= g0b;
                }
            }
        }
        compute(c & (NSTG - 1));
        if (c + 3 < NC) issue(c + 3);   // writes stage (c-1)%4: safe after this sync
    }

    // ----- epilogue: out = acc + g0 * bias -----
#pragma unroll
    for (int mi = 0; mi < 4; mi++) {
        int ra2 = rowBase + wm * 64 + mi * 16 + gid;
#pragma unroll
        for (int half = 0; half < 2; half++) {
            int row = ra2 + half * 8;
            float g0 = g_gates[row * GG];
#pragma unroll
            for (int ni = 0; ni < 8; ni++) {
                int col = colBase + wn * 64 + ni * 8 + tig * 2;
                float2 v;
                v.x = acc[mi][ni][half * 2 + 0] + g0 * bias[col];
                v.y = acc[mi][ni][half * 2 + 1] + g0 * bias[col + 1];
                *(float2*)&out[(size_t)row * OO + col] = v;
            }
        }
    }
}

// ---------------- launcher ----------------
extern "C" void kernel_launch(void* const* d_in, const int* in_sizes, int n_in,
                              void* d_out, int out_size)
{
    const float* x      = (const float*)d_in[0];
    const float* W      = (const float*)d_in[1];
    const float* bias   = (const float*)d_in[2];
    const float* loraA  = (const float*)d_in[3];
    const float* loraB  = (const float*)d_in[4];
    const float* gw     = (const float*)d_in[5];
    // d_in[6] = bvv (unused by the reference computation)
    float* out = (float*)d_out;

    cudaFuncSetAttribute(mma_fused_kernel,
                         cudaFuncAttributeMaxDynamicSharedMemorySize, SMEM_U32 * 4);

    transpose_A_kernel<<<512, 256>>>(loraA);
    gate_kernel<<<NN / 8, 256>>>(x, gw);
    loraA_tc_kernel<<<dim3(NSPLIT, NN / 128), 128>>>(x);
    reduce_t_kernel<<<NN * ER / 4 / 256, 256>>>();
    mma_fused_kernel<<<dim3(OO / 128, NN / 128), 128, SMEM_U32 * 4>>>(x, W, bias, loraB, out);
}